// round 2
// baseline (speedup 1.0000x reference)
#include <cuda_runtime.h>

#define N_Q   2048
#define N_P   256
#define EMB   512
#define NM    5
#define HID   64

// Scratch (allocation-free rule: __device__ globals)
__device__ float g_hq[NM * N_Q * HID];   // (hq + b1), 2.6 MB
__device__ float g_hp[NM * N_P * HID];   // hp,        0.33 MB

// ---------------------------------------------------------------------------
// Kernel 1: fused GEMM for both hq and hp.
//   hq[m,q,h] = sum_d Q[q,d] * W1[m,h,d]        + b1[m,h]
//   hp[m,p,h] = sum_d P[p,d] * W1[m,h,EMB+d]
// grid.x = N_Q/RT + N_P/RT row-tiles, grid.y = m. 720 blocks total.
// ---------------------------------------------------------------------------
#define RT 16
#define KT 32

__global__ __launch_bounds__(256) void gemm_hqp_kernel(
    const float* __restrict__ Q, const float* __restrict__ P,
    const float* __restrict__ W1, const float* __restrict__ b1)
{
    __shared__ float Qs[KT][RT + 4];      // transposed [k][row]
    __shared__ float Ws[KT][HID + 4];     // transposed [k][h]

    const int m  = blockIdx.y;
    const int rt = blockIdx.x;
    const bool is_q = rt < (N_Q / RT);

    const float* src;
    int row0, d_off;
    float* dst;
    if (is_q) {
        src = Q;  row0 = rt * RT;               d_off = 0;
        dst = g_hq + (m * N_Q + row0) * HID;
    } else {
        src = P;  row0 = (rt - N_Q / RT) * RT;  d_off = EMB;
        dst = g_hp + (m * N_P + row0) * HID;
    }

    const int tid = threadIdx.x;
    const int tx  = tid & 15;   // h-group: h = tx*4 .. tx*4+3
    const int ty  = tid >> 4;   // row within tile (0..15)

    float acc0 = 0.f, acc1 = 0.f, acc2 = 0.f, acc3 = 0.f;

    const float* Wbase = W1 + (size_t)(m * HID) * (2 * EMB) + d_off;

    for (int kt = 0; kt < EMB; kt += KT) {
        // Load input row-tile: RT x KT = 512 floats = 128 float4 (threads 0..127)
        if (tid < 128) {
            int r  = tid >> 3;   // 0..15
            int c4 = tid & 7;    // 0..7
            float4 v = *(const float4*)(src + (size_t)(row0 + r) * EMB + kt + c4 * 4);
            Qs[c4 * 4 + 0][r] = v.x;
            Qs[c4 * 4 + 1][r] = v.y;
            Qs[c4 * 4 + 2][r] = v.z;
            Qs[c4 * 4 + 3][r] = v.w;
        }
        // Load W tile: HID x KT = 2048 floats = 512 float4, 2 per thread
        #pragma unroll
        for (int i = 0; i < 2; i++) {
            int idx = tid + i * 256;
            int h   = idx >> 3;  // 0..63
            int c4  = idx & 7;   // 0..7
            float4 v = *(const float4*)(Wbase + (size_t)h * (2 * EMB) + kt + c4 * 4);
            Ws[c4 * 4 + 0][h] = v.x;
            Ws[c4 * 4 + 1][h] = v.y;
            Ws[c4 * 4 + 2][h] = v.z;
            Ws[c4 * 4 + 3][h] = v.w;
        }
        __syncthreads();

        #pragma unroll
        for (int k = 0; k < KT; k++) {
            float  a = Qs[k][ty];
            float4 b = *(const float4*)&Ws[k][tx * 4];
            acc0 += a * b.x;
            acc1 += a * b.y;
            acc2 += a * b.z;
            acc3 += a * b.w;
        }
        __syncthreads();
    }

    float bb0 = 0.f, bb1 = 0.f, bb2 = 0.f, bb3 = 0.f;
    if (is_q) {
        float4 bv = *(const float4*)(b1 + m * HID + tx * 4);
        bb0 = bv.x; bb1 = bv.y; bb2 = bv.z; bb3 = bv.w;
    }
    float4 outv = make_float4(acc0 + bb0, acc1 + bb1, acc2 + bb2, acc3 + bb3);
    *(float4*)(dst + ty * HID + tx * 4) = outv;
}

// ---------------------------------------------------------------------------
// Kernel 2: fused relu-combine + h-reduction + ensemble stats.
//   out[q,p] = mean_m(o) * exp(-std_m(o, ddof=1))
//   o[m]     = b2[m] + sum_h relu(hq[m,q,h] + hp[m,p,h]) * W2[m,h]
// Tile: QT=16 q  x  PT=16 p per block, hq/hp tiles staged in shared.
// grid = (N_Q/QT, N_P/PT) = (128, 16) = 2048 blocks.
// ---------------------------------------------------------------------------
#define QT 16
#define PT 16
#define HPAD (HID + 4)   // stride 68 -> 2-way LDS.128 conflicts max

__global__ __launch_bounds__(256) void final_kernel(
    const float* __restrict__ W2, const float* __restrict__ b2,
    float* __restrict__ out)
{
    __shared__ float s_hq[NM][QT][HPAD];   // 21.76 KB
    __shared__ float s_hp[NM][PT][HPAD];   // 21.76 KB
    __shared__ float s_w2[NM][HID];        // 1.25 KB
    __shared__ float s_b2[NM];

    const int tid = threadIdx.x;
    const int q0  = blockIdx.x * QT;
    const int p0  = blockIdx.y * PT;

    // Stage hq tile: NM*QT rows of HID floats = 1280 float4
    #pragma unroll
    for (int i = tid; i < NM * QT * (HID / 4); i += 256) {
        int c4  = i & 15;          // float4 col
        int row = i >> 4;          // 0..79
        int m   = row / QT;
        int r   = row % QT;
        float4 v = *(const float4*)(g_hq + ((size_t)(m * N_Q + q0 + r)) * HID + c4 * 4);
        *(float4*)&s_hq[m][r][c4 * 4] = v;
    }
    // Stage hp tile
    #pragma unroll
    for (int i = tid; i < NM * PT * (HID / 4); i += 256) {
        int c4  = i & 15;
        int row = i >> 4;
        int m   = row / PT;
        int r   = row % PT;
        float4 v = *(const float4*)(g_hp + ((size_t)(m * N_P + p0 + r)) * HID + c4 * 4);
        *(float4*)&s_hp[m][r][c4 * 4] = v;
    }
    // W2 is NM*HID = 320 floats but block has 256 threads -> grid-stride!
    for (int i = tid; i < NM * HID; i += 256) ((float*)s_w2)[i] = W2[i];
    if (tid < NM) s_b2[tid] = b2[tid];
    __syncthreads();

    const int q_l = tid >> 4;   // 0..15
    const int p_l = tid & 15;   // 0..15

    float o[NM];
    #pragma unroll
    for (int m = 0; m < NM; m++) {
        float a = 0.f;
        #pragma unroll
        for (int h = 0; h < HID; h += 4) {
            float4 x = *(const float4*)&s_hq[m][q_l][h];
            float4 y = *(const float4*)&s_hp[m][p_l][h];
            float4 w = *(const float4*)&s_w2[m][h];
            a += fmaxf(x.x + y.x, 0.f) * w.x;
            a += fmaxf(x.y + y.y, 0.f) * w.y;
            a += fmaxf(x.z + y.z, 0.f) * w.z;
            a += fmaxf(x.w + y.w, 0.f) * w.w;
        }
        o[m] = a + s_b2[m];
    }

    float mean = (o[0] + o[1] + o[2] + o[3] + o[4]) * 0.2f;
    float var = 0.f;
    #pragma unroll
    for (int m = 0; m < NM; m++) {
        float d = o[m] - mean;
        var += d * d;
    }
    var *= 0.25f;                       // ddof = 1
    float unc = sqrtf(var);
    out[(size_t)(q0 + q_l) * N_P + (p0 + p_l)] = mean * expf(-unc);
}

// ---------------------------------------------------------------------------
extern "C" void kernel_launch(void* const* d_in, const int* in_sizes, int n_in,
                              void* d_out, int out_size)
{
    const float* Q  = (const float*)d_in[0];
    const float* P  = (const float*)d_in[1];
    const float* W1 = (const float*)d_in[2];
    const float* b1 = (const float*)d_in[3];
    const float* W2 = (const float*)d_in[4];
    const float* b2 = (const float*)d_in[5];
    float* out = (float*)d_out;

    dim3 g1(N_Q / RT + N_P / RT, NM);   // (144, 5) = 720 blocks
    gemm_hqp_kernel<<<g1, 256>>>(Q, P, W1, b1);

    dim3 g2(N_Q / QT, N_P / PT);        // (128, 16) = 2048 blocks
    final_kernel<<<g2, 256>>>(W2, b2, out);
}

// round 3
// speedup vs baseline: 1.6085x; 1.6085x over previous
#include <cuda_runtime.h>

#define N_Q   2048
#define N_P   256
#define EMB   512
#define NM    5
#define HID   64
#define KSPLIT 2
#define KHALF (EMB / KSPLIT)     // 256

// Scratch: K-split partial sums (allocation-free rule: __device__ globals)
__device__ float g_hq[KSPLIT][NM * N_Q * HID];   // 2 x 2.62 MB
__device__ float g_hp[KSPLIT][NM * N_P * HID];   // 2 x 0.33 MB

// ---------------------------------------------------------------------------
// Kernel 1: GEMM partials.
//   part[kh][m,row,h] = sum_{d in half kh} X[row,d] * W1[m,h,(off)+d]  (+b1 on kh==0 for Q)
// Tile: 32 rows x 64 h, 128 threads, 4x4 outputs/thread, K-tile 32.
// grid = (72, 5, 2) = 720 blocks.
// ---------------------------------------------------------------------------
#define GRT 32
#define GKT 32

__global__ __launch_bounds__(128) void gemm_hqp_kernel(
    const float* __restrict__ Q, const float* __restrict__ P,
    const float* __restrict__ W1, const float* __restrict__ b1)
{
    // Flat XOR-swizzled tiles (transposed: [k][row] / [k][h])
    __shared__ float Qs[GKT * GRT];   // 4 KB
    __shared__ float Ws[GKT * HID];   // 8 KB

    const int m  = blockIdx.y;
    const int kh = blockIdx.z;
    const int rt = blockIdx.x;
    const bool is_q = rt < (N_Q / GRT);

    const float* src;
    int row0;
    float* dst;
    if (is_q) {
        src = Q;  row0 = rt * GRT;
        dst = &g_hq[kh][(size_t)(m * N_Q + row0) * HID];
    } else {
        src = P;  row0 = (rt - N_Q / GRT) * GRT;
        dst = &g_hp[kh][(size_t)(m * N_P + row0) * HID];
    }
    const float* Sb = src + (size_t)row0 * EMB + kh * KHALF;
    const float* Wb = W1 + (size_t)m * HID * (2 * EMB) + (is_q ? 0 : EMB) + kh * KHALF;

    const int tid = threadIdx.x;
    const int tx  = tid & 15;    // h-group: c0 = tx*4
    const int ty  = tid >> 4;    // row-group: r0 = ty*4 (0..7)

    float acc[4][4] = {};

    for (int kt = 0; kt < KHALF; kt += GKT) {
        // Stage input tile: 32 rows x 32 k = 256 float4, 2 per thread.
        // Swizzled store: word = k*32 + (((r>>2) ^ (k&7)) << 2) + (r&3)
        #pragma unroll
        for (int i = 0; i < 2; i++) {
            int idx = tid + i * 128;
            int r   = idx >> 3;   // 0..31
            int c4  = idx & 7;    // 0..7
            float4 v = *(const float4*)(Sb + (size_t)r * EMB + kt + c4 * 4);
            const float* vf = (const float*)&v;
            #pragma unroll
            for (int j = 0; j < 4; j++) {
                int k = c4 * 4 + j;
                Qs[k * GRT + ((((r >> 2) ^ (k & 7)) << 2) | (r & 3))] = vf[j];
            }
        }
        // Stage W tile: 64 h x 32 k = 512 float4, 4 per thread.
        // Swizzled store: word = k*64 + (((h>>2) ^ (k&15)) << 2) + (h&3)
        #pragma unroll
        for (int i = 0; i < 4; i++) {
            int idx = tid + i * 128;
            int h   = idx >> 3;   // 0..63
            int c4  = idx & 7;
            float4 v = *(const float4*)(Wb + (size_t)h * (2 * EMB) + kt + c4 * 4);
            const float* vf = (const float*)&v;
            #pragma unroll
            for (int j = 0; j < 4; j++) {
                int k = c4 * 4 + j;
                Ws[k * HID + ((((h >> 2) ^ (k & 15)) << 2) | (h & 3))] = vf[j];
            }
        }
        __syncthreads();

        #pragma unroll
        for (int k = 0; k < GKT; k++) {
            float4 a = *(const float4*)&Qs[k * GRT + ((ty ^ (k & 7)) << 2)];
            float4 b = *(const float4*)&Ws[k * HID + ((tx ^ (k & 15)) << 2)];
            const float* af = (const float*)&a;
            const float* bf = (const float*)&b;
            #pragma unroll
            for (int i = 0; i < 4; i++)
                #pragma unroll
                for (int j = 0; j < 4; j++)
                    acc[i][j] += af[i] * bf[j];
        }
        __syncthreads();
    }

    if (is_q && kh == 0) {
        float4 bv = *(const float4*)(b1 + m * HID + tx * 4);
        #pragma unroll
        for (int i = 0; i < 4; i++) {
            acc[i][0] += bv.x; acc[i][1] += bv.y;
            acc[i][2] += bv.z; acc[i][3] += bv.w;
        }
    }
    #pragma unroll
    for (int i = 0; i < 4; i++)
        *(float4*)(dst + (size_t)(ty * 4 + i) * HID + tx * 4) =
            make_float4(acc[i][0], acc[i][1], acc[i][2], acc[i][3]);
}

// ---------------------------------------------------------------------------
// Kernel 2: fused relu-combine + h-reduction + ensemble stats.
// Tile: 32q x 32p per block, 256 threads, 2x2 outputs/thread.
// Staging sums the two K-split partials. grid = (64, 8) = 512 blocks.
// ---------------------------------------------------------------------------
#define QT 32
#define PT 32
#define HPAD (HID + 4)

#define SMEM_FLOATS (NM*QT*HPAD + NM*PT*HPAD + NM*HID + 8)
#define SMEM_BYTES  (SMEM_FLOATS * 4)

__global__ __launch_bounds__(256) void final_kernel(
    const float* __restrict__ W2, const float* __restrict__ b2,
    float* __restrict__ out)
{
    extern __shared__ float smem_f[];
    float* s_hq = smem_f;                       // [NM][QT][HPAD]
    float* s_hp = s_hq + NM * QT * HPAD;        // [NM][PT][HPAD]
    float* s_w2 = s_hp + NM * PT * HPAD;        // [NM][HID]
    float* s_b2 = s_w2 + NM * HID;              // [NM]

    const int tid = threadIdx.x;
    const int q0  = blockIdx.x * QT;
    const int p0  = blockIdx.y * PT;

    // Stage hq tile (sum K-split partials): NM*QT rows x 16 float4 = 2560
    for (int i = tid; i < NM * QT * (HID / 4); i += 256) {
        int c4  = i & 15;
        int row = i >> 4;         // 0..159
        int m   = row >> 5;
        int r   = row & 31;
        size_t g = ((size_t)(m * N_Q + q0 + r)) * HID + c4 * 4;
        float4 v0 = *(const float4*)(&g_hq[0][g]);
        float4 v1 = *(const float4*)(&g_hq[1][g]);
        *(float4*)&s_hq[(m * QT + r) * HPAD + c4 * 4] =
            make_float4(v0.x + v1.x, v0.y + v1.y, v0.z + v1.z, v0.w + v1.w);
    }
    // Stage hp tile: 2560 float4
    for (int i = tid; i < NM * PT * (HID / 4); i += 256) {
        int c4  = i & 15;
        int row = i >> 4;
        int m   = row >> 5;
        int r   = row & 31;
        size_t g = ((size_t)(m * N_P + p0 + r)) * HID + c4 * 4;
        float4 v0 = *(const float4*)(&g_hp[0][g]);
        float4 v1 = *(const float4*)(&g_hp[1][g]);
        *(float4*)&s_hp[(m * PT + r) * HPAD + c4 * 4] =
            make_float4(v0.x + v1.x, v0.y + v1.y, v0.z + v1.z, v0.w + v1.w);
    }
    for (int i = tid; i < NM * HID; i += 256) s_w2[i] = W2[i];
    if (tid < NM) s_b2[tid] = b2[tid];
    __syncthreads();

    const int qb = (tid >> 4) << 1;   // 0,2,..,30
    const int pb = (tid & 15) << 1;

    float o[NM][4];
    #pragma unroll
    for (int m = 0; m < NM; m++) {
        float a00 = 0.f, a01 = 0.f, a10 = 0.f, a11 = 0.f;
        const float* xq0 = &s_hq[(m * QT + qb) * HPAD];
        const float* xq1 = xq0 + HPAD;
        const float* yp0 = &s_hp[(m * PT + pb) * HPAD];
        const float* yp1 = yp0 + HPAD;
        const float* w   = &s_w2[m * HID];
        #pragma unroll 4
        for (int h = 0; h < HID; h += 4) {
            float4 x0 = *(const float4*)(xq0 + h);
            float4 x1 = *(const float4*)(xq1 + h);
            float4 y0 = *(const float4*)(yp0 + h);
            float4 y1 = *(const float4*)(yp1 + h);
            float4 wv = *(const float4*)(w + h);
            a00 += fmaxf(x0.x + y0.x, 0.f) * wv.x;
            a01 += fmaxf(x0.x + y1.x, 0.f) * wv.x;
            a10 += fmaxf(x1.x + y0.x, 0.f) * wv.x;
            a11 += fmaxf(x1.x + y1.x, 0.f) * wv.x;
            a00 += fmaxf(x0.y + y0.y, 0.f) * wv.y;
            a01 += fmaxf(x0.y + y1.y, 0.f) * wv.y;
            a10 += fmaxf(x1.y + y0.y, 0.f) * wv.y;
            a11 += fmaxf(x1.y + y1.y, 0.f) * wv.y;
            a00 += fmaxf(x0.z + y0.z, 0.f) * wv.z;
            a01 += fmaxf(x0.z + y1.z, 0.f) * wv.z;
            a10 += fmaxf(x1.z + y0.z, 0.f) * wv.z;
            a11 += fmaxf(x1.z + y1.z, 0.f) * wv.z;
            a00 += fmaxf(x0.w + y0.w, 0.f) * wv.w;
            a01 += fmaxf(x0.w + y1.w, 0.f) * wv.w;
            a10 += fmaxf(x1.w + y0.w, 0.f) * wv.w;
            a11 += fmaxf(x1.w + y1.w, 0.f) * wv.w;
        }
        float bb = s_b2[m];
        o[m][0] = a00 + bb; o[m][1] = a01 + bb;
        o[m][2] = a10 + bb; o[m][3] = a11 + bb;
    }

    #pragma unroll
    for (int j = 0; j < 4; j++) {
        float mean = (o[0][j] + o[1][j] + o[2][j] + o[3][j] + o[4][j]) * 0.2f;
        float var = 0.f;
        #pragma unroll
        for (int m = 0; m < NM; m++) {
            float d = o[m][j] - mean;
            var += d * d;
        }
        var *= 0.25f;   // ddof = 1
        float r = mean * expf(-sqrtf(var));
        int q = q0 + qb + (j >> 1);
        int p = p0 + pb + (j & 1);
        out[(size_t)q * N_P + p] = r;
    }
}

// ---------------------------------------------------------------------------
extern "C" void kernel_launch(void* const* d_in, const int* in_sizes, int n_in,
                              void* d_out, int out_size)
{
    const float* Q  = (const float*)d_in[0];
    const float* P  = (const float*)d_in[1];
    const float* W1 = (const float*)d_in[2];
    const float* b1 = (const float*)d_in[3];
    const float* W2 = (const float*)d_in[4];
    const float* b2 = (const float*)d_in[5];
    float* out = (float*)d_out;

    dim3 g1(N_Q / GRT + N_P / GRT, NM, KSPLIT);   // (72, 5, 2) = 720 blocks
    gemm_hqp_kernel<<<g1, 128>>>(Q, P, W1, b1);

    cudaFuncSetAttribute(final_kernel,
                         cudaFuncAttributeMaxDynamicSharedMemorySize, SMEM_BYTES);
    dim3 g2(N_Q / QT, N_P / PT);                  // (64, 8) = 512 blocks
    final_kernel<<<g2, 256, SMEM_BYTES>>>(W2, b2, out);
}

// round 4
// speedup vs baseline: 1.7843x; 1.1093x over previous
#include <cuda_runtime.h>
#include <cstdint>

#define N_Q   2048
#define N_P   256
#define EMB   512
#define NM    5
#define HID   64
#define KSPLIT 2
#define KHALF (EMB / KSPLIT)     // 256

// Scratch (allocation-free rule: __device__ globals)
__device__ float g_hq[KSPLIT][NM * N_Q * HID];   // partials
__device__ float g_hp[KSPLIT][NM * N_P * HID];
__device__ float g_hqs[NM * N_Q * HID];          // summed
__device__ float g_hps[NM * N_P * HID];

// ---------------------------------------------------------------------------
// Kernel 1: GEMM partials (unchanged from R3 — measured at dual roofline).
// ---------------------------------------------------------------------------
#define GRT 32
#define GKT 32

__global__ __launch_bounds__(128) void gemm_hqp_kernel(
    const float* __restrict__ Q, const float* __restrict__ P,
    const float* __restrict__ W1, const float* __restrict__ b1)
{
    __shared__ float Qs[GKT * GRT];
    __shared__ float Ws[GKT * HID];

    const int m  = blockIdx.y;
    const int kh = blockIdx.z;
    const int rt = blockIdx.x;
    const bool is_q = rt < (N_Q / GRT);

    const float* src;
    int row0;
    float* dst;
    if (is_q) {
        src = Q;  row0 = rt * GRT;
        dst = &g_hq[kh][(size_t)(m * N_Q + row0) * HID];
    } else {
        src = P;  row0 = (rt - N_Q / GRT) * GRT;
        dst = &g_hp[kh][(size_t)(m * N_P + row0) * HID];
    }
    const float* Sb = src + (size_t)row0 * EMB + kh * KHALF;
    const float* Wb = W1 + (size_t)m * HID * (2 * EMB) + (is_q ? 0 : EMB) + kh * KHALF;

    const int tid = threadIdx.x;
    const int tx  = tid & 15;
    const int ty  = tid >> 4;

    float acc[4][4] = {};

    for (int kt = 0; kt < KHALF; kt += GKT) {
        #pragma unroll
        for (int i = 0; i < 2; i++) {
            int idx = tid + i * 128;
            int r   = idx >> 3;
            int c4  = idx & 7;
            float4 v = *(const float4*)(Sb + (size_t)r * EMB + kt + c4 * 4);
            const float* vf = (const float*)&v;
            #pragma unroll
            for (int j = 0; j < 4; j++) {
                int k = c4 * 4 + j;
                Qs[k * GRT + ((((r >> 2) ^ (k & 7)) << 2) | (r & 3))] = vf[j];
            }
        }
        #pragma unroll
        for (int i = 0; i < 4; i++) {
            int idx = tid + i * 128;
            int h   = idx >> 3;
            int c4  = idx & 7;
            float4 v = *(const float4*)(Wb + (size_t)h * (2 * EMB) + kt + c4 * 4);
            const float* vf = (const float*)&v;
            #pragma unroll
            for (int j = 0; j < 4; j++) {
                int k = c4 * 4 + j;
                Ws[k * HID + ((((h >> 2) ^ (k & 15)) << 2) | (h & 3))] = vf[j];
            }
        }
        __syncthreads();

        #pragma unroll
        for (int k = 0; k < GKT; k++) {
            float4 a = *(const float4*)&Qs[k * GRT + ((ty ^ (k & 7)) << 2)];
            float4 b = *(const float4*)&Ws[k * HID + ((tx ^ (k & 15)) << 2)];
            const float* af = (const float*)&a;
            const float* bf = (const float*)&b;
            #pragma unroll
            for (int i = 0; i < 4; i++)
                #pragma unroll
                for (int j = 0; j < 4; j++)
                    acc[i][j] += af[i] * bf[j];
        }
        __syncthreads();
    }

    if (is_q && kh == 0) {
        float4 bv = *(const float4*)(b1 + m * HID + tx * 4);
        #pragma unroll
        for (int i = 0; i < 4; i++) {
            acc[i][0] += bv.x; acc[i][1] += bv.y;
            acc[i][2] += bv.z; acc[i][3] += bv.w;
        }
    }
    #pragma unroll
    for (int i = 0; i < 4; i++)
        *(float4*)(dst + (size_t)(ty * 4 + i) * HID + tx * 4) =
            make_float4(acc[i][0], acc[i][1], acc[i][2], acc[i][3]);
}

// ---------------------------------------------------------------------------
// Kernel 2: sum the K-split partials into single buffers (tiny, ~1us).
// ---------------------------------------------------------------------------
#define HQ4 (NM * N_Q * HID / 4)   // 163840 float4
#define HP4 (NM * N_P * HID / 4)   // 20480  float4

__global__ __launch_bounds__(256) void sum_partials_kernel()
{
    int i = blockIdx.x * 256 + threadIdx.x;
    if (i < HQ4) {
        float4 a = ((const float4*)g_hq[0])[i];
        float4 b = ((const float4*)g_hq[1])[i];
        ((float4*)g_hqs)[i] = make_float4(a.x + b.x, a.y + b.y, a.z + b.z, a.w + b.w);
    } else {
        int j = i - HQ4;
        float4 a = ((const float4*)g_hp[0])[j];
        float4 b = ((const float4*)g_hp[1])[j];
        ((float4*)g_hps)[j] = make_float4(a.x + b.x, a.y + b.y, a.z + b.z, a.w + b.w);
    }
}

// ---------------------------------------------------------------------------
// Kernel 3: fused relu-combine + h-reduction + ensemble stats.
// Tile: 64q x 64p, 256 threads (16x16), 4x4 outputs/thread.
// Per-m double-buffered cp.async staging; packed f32x2 relu-FMA.
// grid = (32, 4) = 128 blocks.
// ---------------------------------------------------------------------------
#define BQ 64
#define BP 64

// smem: 2 bufs x (x:64x64 + y:64x64) + w2 + b2
#define BUF_FLOATS (2 * BQ * HID)                 // one buffer (x then y)
#define SMEM_FLOATS (2 * BUF_FLOATS + NM * HID + 8)
#define SMEM_BYTES  (SMEM_FLOATS * 4)

// relu(s)*w accumulation, packed 2 x fp32:
//   relu(s) * w == (s + |s|) * (w * 0.5)   (bit-exact: *2 and *0.5 are exact)
#define RELU_FMA2(acc, x2, y2, w2)                                    \
    asm("{\n\t"                                                       \
        ".reg .b64 s, a;\n\t"                                         \
        "add.rn.f32x2 s, %1, %2;\n\t"                                 \
        "and.b64 a, s, 0x7FFFFFFF7FFFFFFF;\n\t"                       \
        "add.rn.f32x2 s, s, a;\n\t"                                   \
        "fma.rn.f32x2 %0, s, %3, %0;\n\t"                             \
        "}"                                                           \
        : "+l"(acc) : "l"(x2), "l"(y2), "l"(w2))

__device__ __forceinline__ void cpa16(void* smem_ptr, const void* gptr) {
    uint32_t s = (uint32_t)__cvta_generic_to_shared(smem_ptr);
    asm volatile("cp.async.cg.shared.global [%0], [%1], 16;" :: "r"(s), "l"(gptr));
}

__global__ __launch_bounds__(256) void final_kernel(
    const float* __restrict__ W2, const float* __restrict__ b2,
    float* __restrict__ out)
{
    extern __shared__ float smem_f[];
    // buf[b]: x tile at smem_f + b*BUF_FLOATS, y tile at + BQ*HID
    float* s_w2 = smem_f + 2 * BUF_FLOATS;
    float* s_b2 = s_w2 + NM * HID;

    const int tid = threadIdx.x;
    const int q0  = blockIdx.x * BQ;
    const int p0  = blockIdx.y * BP;
    const int ty  = tid >> 4;   // 0..15 -> q rows ty*4..ty*4+3
    const int tx  = tid & 15;   // 0..15 -> p rows tx*4..tx*4+3

    // stage W2 (prescaled by 0.5) and b2 once
    for (int i = tid; i < NM * HID; i += 256) s_w2[i] = 0.5f * W2[i];
    if (tid < NM) s_b2[tid] = b2[tid];

    // per-thread staging slot: 8 float4 per m
    // idx = tid + k*256 (0..2047): a = idx>>10 (0:x,1:y), row = (idx>>4)&63, c4 = idx&15
    auto stage = [&](int m, int b) {
        float* base = smem_f + b * BUF_FLOATS;
        #pragma unroll
        for (int k = 0; k < 8; k++) {
            int idx = tid + k * 256;
            int a   = idx >> 10;
            int row = (idx >> 4) & 63;
            int c4  = idx & 15;
            int sc  = (c4 ^ ((row >> 2) & 15)) * 4;
            const float* g;
            float* s;
            if (a == 0) {
                g = g_hqs + ((size_t)(m * N_Q + q0 + row)) * HID + c4 * 4;
                s = base + row * HID + sc;
            } else {
                g = g_hps + ((size_t)(m * N_P + p0 + row)) * HID + c4 * 4;
                s = base + BQ * HID + row * HID + sc;
            }
            cpa16(s, g);
        }
        asm volatile("cp.async.commit_group;");
    };

    stage(0, 0);

    float sum[4][4] = {};
    float sq [4][4] = {};

    const int swx = (ty >> 2) & 15;   // row>>2 for x rows (rows ty*4+i -> (ty*4+i)>>2 = ty)
    const int swy = tx;               // row>>2 for y rows (rows tx*4+j -> tx)

    for (int m = 0; m < NM; m++) {
        if (m + 1 < NM) {
            stage(m + 1, (m + 1) & 1);
            asm volatile("cp.async.wait_group 1;");
        } else {
            asm volatile("cp.async.wait_group 0;");
        }
        __syncthreads();

        const float* bx = smem_f + (m & 1) * BUF_FLOATS;
        const float* by = bx + BQ * HID;
        const float* xrow = bx + (ty * 4) * HID;   // 4 consecutive rows
        const float* yrow = by + (tx * 4) * HID;
        const float* wrow = s_w2 + m * HID;

        unsigned long long acc[4][4] = {};

        #pragma unroll 4
        for (int c4 = 0; c4 < 16; c4++) {
            // swizzled columns (x rows share ty as row>>2; y rows share tx)
            int cx = (c4 ^ ty) * 4;       // note: ty = row>>2 for all 4 x rows
            int cy = (c4 ^ tx) * 4;
            ulonglong2 X[4], Y[4];
            #pragma unroll
            for (int i = 0; i < 4; i++)
                X[i] = *(const ulonglong2*)(xrow + i * HID + cx);
            #pragma unroll
            for (int j = 0; j < 4; j++)
                Y[j] = *(const ulonglong2*)(yrow + j * HID + cy);
            ulonglong2 Wv = *(const ulonglong2*)(wrow + c4 * 4);

            #pragma unroll
            for (int i = 0; i < 4; i++)
                #pragma unroll
                for (int j = 0; j < 4; j++) {
                    RELU_FMA2(acc[i][j], X[i].x, Y[j].x, Wv.x);
                    RELU_FMA2(acc[i][j], X[i].y, Y[j].y, Wv.y);
                }
        }

        float bb = s_b2[m];
        #pragma unroll
        for (int i = 0; i < 4; i++)
            #pragma unroll
            for (int j = 0; j < 4; j++) {
                unsigned long long a = acc[i][j];
                float lo = __uint_as_float((unsigned)(a & 0xFFFFFFFFull));
                float hi = __uint_as_float((unsigned)(a >> 32));
                float o  = lo + hi + bb;
                sum[i][j] += o;
                sq [i][j] += o * o;
            }

        __syncthreads();   // buffer (m&1) free for stage(m+2)
    }

    #pragma unroll
    for (int i = 0; i < 4; i++)
        #pragma unroll
        for (int j = 0; j < 4; j++) {
            float mean = sum[i][j] * 0.2f;
            float var  = fmaxf(sq[i][j] - 5.0f * mean * mean, 0.0f) * 0.25f; // ddof=1
            float r    = mean * expf(-sqrtf(var));
            int q = q0 + ty * 4 + i;
            int p = p0 + tx * 4 + j;
            out[(size_t)q * N_P + p] = r;
        }
}

// ---------------------------------------------------------------------------
extern "C" void kernel_launch(void* const* d_in, const int* in_sizes, int n_in,
                              void* d_out, int out_size)
{
    const float* Q  = (const float*)d_in[0];
    const float* P  = (const float*)d_in[1];
    const float* W1 = (const float*)d_in[2];
    const float* b1 = (const float*)d_in[3];
    const float* W2 = (const float*)d_in[4];
    const float* b2 = (const float*)d_in[5];
    float* out = (float*)d_out;

    dim3 g1(N_Q / GRT + N_P / GRT, NM, KSPLIT);   // (72, 5, 2) = 720 blocks
    gemm_hqp_kernel<<<g1, 128>>>(Q, P, W1, b1);

    sum_partials_kernel<<<(HQ4 + HP4) / 256, 256>>>();   // 720 blocks

    cudaFuncSetAttribute(final_kernel,
                         cudaFuncAttributeMaxDynamicSharedMemorySize, SMEM_BYTES);
    dim3 g3(N_Q / BQ, N_P / BP);                  // (32, 4) = 128 blocks
    final_kernel<<<g3, 256, SMEM_BYTES>>>(W2, b2, out);
}

// round 5
// speedup vs baseline: 1.9455x; 1.0903x over previous
#include <cuda_runtime.h>
#include <cstdint>

#define N_Q   2048
#define N_P   256
#define EMB   512
#define NM    5
#define HID   64
#define KSPLIT 8
#define GK    (EMB / KSPLIT)     // 64 K per gemm block

// Scratch (allocation-free rule: __device__ globals)
__device__ float g_hq[KSPLIT][NM * N_Q * HID];   // partials, 8 x 2.62 MB
__device__ float g_hp[KSPLIT][NM * N_P * HID];   // partials, 8 x 0.33 MB
__device__ float g_hqs[NM * N_Q * HID];          // summed
__device__ float g_hps[NM * N_P * HID];

// ---------------------------------------------------------------------------
// Kernel 1: GEMM partials.
// Tile: 128 rows x 64 h, 256 threads, 8x4 outputs/thread, K=64 per block.
// Whole-K staged once (no mid-loop syncs). grid = (18, 5, 8) = 720 blocks.
// Swizzled k-major shared layout:
//   As[k][col],  col = (row&3) | (((row>>2) ^ ((k>>2)&7)) << 2)   (row 0..127)
//   Ws[k][colh], colh = (h&3)  | ((((h>>2) ^ ((k>>2)&7)) & 15) << 2)
// ---------------------------------------------------------------------------
#define GR 128

__global__ __launch_bounds__(256) void gemm_hqp_kernel(
    const float* __restrict__ Q, const float* __restrict__ P,
    const float* __restrict__ W1, const float* __restrict__ b1)
{
    __shared__ float As[GK * GR];   // 32 KB
    __shared__ float Ws[GK * HID];  // 16 KB

    const int m  = blockIdx.y;
    const int kh = blockIdx.z;
    const int rt = blockIdx.x;
    const bool is_q = rt < (N_Q / GR);   // 16 q-tiles, 2 p-tiles

    const float* src;
    int row0;
    float* dst;
    if (is_q) {
        src = Q;  row0 = rt * GR;
        dst = &g_hq[kh][(size_t)(m * N_Q + row0) * HID];
    } else {
        src = P;  row0 = (rt - N_Q / GR) * GR;
        dst = &g_hp[kh][(size_t)(m * N_P + row0) * HID];
    }
    const float* Sb = src + (size_t)row0 * EMB + kh * GK;
    const float* Wb = W1 + (size_t)m * HID * (2 * EMB) + (is_q ? 0 : EMB) + kh * GK;

    const int tid = threadIdx.x;
    const int tx  = tid & 15;    // h-group: h = tx*4 .. +3
    const int ty  = tid >> 4;    // row-group: rows ty*8 .. +7

    // --- Stage input tile: 128 rows x 64 k = 2048 float4, 8 per thread ---
    #pragma unroll
    for (int it = 0; it < 8; it++) {
        int idx = tid + it * 256;
        int row = idx >> 4;          // 0..127
        int c4  = idx & 15;          // 0..15 (k-chunk)
        float4 v = *(const float4*)(Sb + (size_t)row * EMB + c4 * 4);
        int col = (row & 3) | ((((row >> 2) ^ (c4 & 7)) & 31) << 2);
        const float* vf = (const float*)&v;
        #pragma unroll
        for (int j = 0; j < 4; j++)
            As[(c4 * 4 + j) * GR + col] = vf[j];
    }
    // --- Stage W tile: 64 h x 64 k = 1024 float4, 4 per thread ---
    #pragma unroll
    for (int it = 0; it < 4; it++) {
        int idx = tid + it * 256;
        int h   = idx >> 4;          // 0..63
        int c4  = idx & 15;
        float4 v = *(const float4*)(Wb + (size_t)h * (2 * EMB) + c4 * 4);
        int colh = (h & 3) | ((((h >> 2) ^ (c4 & 7)) & 15) << 2);
        const float* vf = (const float*)&v;
        #pragma unroll
        for (int j = 0; j < 4; j++)
            Ws[(c4 * 4 + j) * HID + colh] = vf[j];
    }
    __syncthreads();

    float acc[8][4] = {};

    #pragma unroll 4
    for (int k4 = 0; k4 < 16; k4++) {
        const int s  = k4 & 7;
        const int ca0 = (((ty * 2 + 0) ^ s) & 31) << 2;
        const int ca1 = (((ty * 2 + 1) ^ s) & 31) << 2;
        const int cb  = ((tx ^ s) & 15) << 2;
        #pragma unroll
        for (int j = 0; j < 4; j++) {
            const int k = k4 * 4 + j;
            float4 a0 = *(const float4*)&As[k * GR + ca0];   // rows ty*8..+3
            float4 a1 = *(const float4*)&As[k * GR + ca1];   // rows ty*8+4..+7
            float4 b  = *(const float4*)&Ws[k * HID + cb];   // h tx*4..+3
            const float* af0 = (const float*)&a0;
            const float* af1 = (const float*)&a1;
            const float* bf  = (const float*)&b;
            #pragma unroll
            for (int i = 0; i < 4; i++)
                #pragma unroll
                for (int c = 0; c < 4; c++) {
                    acc[i][c]     += af0[i] * bf[c];
                    acc[i + 4][c] += af1[i] * bf[c];
                }
        }
    }

    if (is_q && kh == 0) {
        float4 bv = *(const float4*)(b1 + m * HID + tx * 4);
        #pragma unroll
        for (int i = 0; i < 8; i++) {
            acc[i][0] += bv.x; acc[i][1] += bv.y;
            acc[i][2] += bv.z; acc[i][3] += bv.w;
        }
    }
    #pragma unroll
    for (int i = 0; i < 8; i++)
        *(float4*)(dst + (size_t)(ty * 8 + i) * HID + tx * 4) =
            make_float4(acc[i][0], acc[i][1], acc[i][2], acc[i][3]);
}

// ---------------------------------------------------------------------------
// Kernel 2: sum the 8 K-split partials (L2-resident, ~3us).
// ---------------------------------------------------------------------------
#define HQ4 (NM * N_Q * HID / 4)   // 163840 float4
#define HP4 (NM * N_P * HID / 4)   // 20480  float4

__global__ __launch_bounds__(256) void sum_partials_kernel()
{
    int i = blockIdx.x * 256 + threadIdx.x;
    if (i < HQ4) {
        float4 a = ((const float4*)g_hq[0])[i];
        #pragma unroll
        for (int s = 1; s < KSPLIT; s++) {
            float4 b = ((const float4*)g_hq[s])[i];
            a.x += b.x; a.y += b.y; a.z += b.z; a.w += b.w;
        }
        ((float4*)g_hqs)[i] = a;
    } else {
        int j = i - HQ4;
        float4 a = ((const float4*)g_hp[0])[j];
        #pragma unroll
        for (int s = 1; s < KSPLIT; s++) {
            float4 b = ((const float4*)g_hp[s])[j];
            a.x += b.x; a.y += b.y; a.z += b.z; a.w += b.w;
        }
        ((float4*)g_hps)[j] = a;
    }
}

// ---------------------------------------------------------------------------
// Kernel 3: fused relu-combine + h-reduction + ensemble stats.
// Tile: 64q x 64p, 256 threads, 4x4 outputs/thread.
// Per-m TRIPLE-buffered cp.async staging (prefetch depth 2); f32x2 relu-FMA.
// grid = (32, 4) = 128 blocks.
// ---------------------------------------------------------------------------
#define BQ 64
#define BP 64

#define BUF_FLOATS (2 * BQ * HID)                 // one buffer (x then y) = 32KB
#define SMEM_FLOATS (3 * BUF_FLOATS + NM * HID + 8)
#define SMEM_BYTES  (SMEM_FLOATS * 4)

// relu(s)*w accumulation, packed 2 x fp32:
//   relu(s) * w == (s + |s|) * (w * 0.5)   (bit-exact: *2 and *0.5 are exact)
#define RELU_FMA2(acc, x2, y2, w2)                                    \
    asm("{\n\t"                                                       \
        ".reg .b64 s, a;\n\t"                                         \
        "add.rn.f32x2 s, %1, %2;\n\t"                                 \
        "and.b64 a, s, 0x7FFFFFFF7FFFFFFF;\n\t"                       \
        "add.rn.f32x2 s, s, a;\n\t"                                   \
        "fma.rn.f32x2 %0, s, %3, %0;\n\t"                             \
        "}"                                                           \
        : "+l"(acc) : "l"(x2), "l"(y2), "l"(w2))

__device__ __forceinline__ void cpa16(void* smem_ptr, const void* gptr) {
    uint32_t s = (uint32_t)__cvta_generic_to_shared(smem_ptr);
    asm volatile("cp.async.cg.shared.global [%0], [%1], 16;" :: "r"(s), "l"(gptr));
}

__global__ __launch_bounds__(256) void final_kernel(
    const float* __restrict__ W2, const float* __restrict__ b2,
    float* __restrict__ out)
{
    extern __shared__ float smem_f[];
    float* s_w2 = smem_f + 3 * BUF_FLOATS;
    float* s_b2 = s_w2 + NM * HID;

    const int tid = threadIdx.x;
    const int q0  = blockIdx.x * BQ;
    const int p0  = blockIdx.y * BP;
    const int ty  = tid >> 4;   // 0..15 -> q rows ty*4..+3
    const int tx  = tid & 15;   // 0..15 -> p rows tx*4..+3

    for (int i = tid; i < NM * HID; i += 256) s_w2[i] = 0.5f * W2[i];
    if (tid < NM) s_b2[tid] = b2[tid];

    auto stage = [&](int m, int b) {
        float* base = smem_f + b * BUF_FLOATS;
        #pragma unroll
        for (int k = 0; k < 8; k++) {
            int idx = tid + k * 256;
            int a   = idx >> 10;
            int row = (idx >> 4) & 63;
            int c4  = idx & 15;
            int sc  = (c4 ^ ((row >> 2) & 15)) * 4;
            const float* g;
            float* s;
            if (a == 0) {
                g = g_hqs + ((size_t)(m * N_Q + q0 + row)) * HID + c4 * 4;
                s = base + row * HID + sc;
            } else {
                g = g_hps + ((size_t)(m * N_P + p0 + row)) * HID + c4 * 4;
                s = base + BQ * HID + row * HID + sc;
            }
            cpa16(s, g);
        }
        asm volatile("cp.async.commit_group;");
    };

    stage(0, 0);
    stage(1, 1);

    float sum[4][4] = {};
    float sq [4][4] = {};

    for (int m = 0; m < NM; m++) {
        if (m + 2 < NM) {
            stage(m + 2, (m + 2) % 3);
            asm volatile("cp.async.wait_group 2;");
        } else if (m + 1 < NM) {
            asm volatile("cp.async.wait_group 1;");
        } else {
            asm volatile("cp.async.wait_group 0;");
        }
        __syncthreads();

        const float* bx = smem_f + (m % 3) * BUF_FLOATS;
        const float* by = bx + BQ * HID;
        const float* xrow = bx + (ty * 4) * HID;
        const float* yrow = by + (tx * 4) * HID;
        const float* wrow = s_w2 + m * HID;

        unsigned long long acc[4][4] = {};

        #pragma unroll 4
        for (int c4 = 0; c4 < 16; c4++) {
            int cx = (c4 ^ ty) * 4;
            int cy = (c4 ^ tx) * 4;
            ulonglong2 X[4], Y[4];
            #pragma unroll
            for (int i = 0; i < 4; i++)
                X[i] = *(const ulonglong2*)(xrow + i * HID + cx);
            #pragma unroll
            for (int j = 0; j < 4; j++)
                Y[j] = *(const ulonglong2*)(yrow + j * HID + cy);
            ulonglong2 Wv = *(const ulonglong2*)(wrow + c4 * 4);

            #pragma unroll
            for (int i = 0; i < 4; i++)
                #pragma unroll
                for (int j = 0; j < 4; j++) {
                    RELU_FMA2(acc[i][j], X[i].x, Y[j].x, Wv.x);
                    RELU_FMA2(acc[i][j], X[i].y, Y[j].y, Wv.y);
                }
        }

        float bb = s_b2[m];
        #pragma unroll
        for (int i = 0; i < 4; i++)
            #pragma unroll
            for (int j = 0; j < 4; j++) {
                unsigned long long a = acc[i][j];
                float lo = __uint_as_float((unsigned)(a & 0xFFFFFFFFull));
                float hi = __uint_as_float((unsigned)(a >> 32));
                float o  = lo + hi + bb;
                sum[i][j] += o;
                sq [i][j] += o * o;
            }

        __syncthreads();   // buf m%3 free: stage(m+3) at next iter writes it
    }

    #pragma unroll
    for (int i = 0; i < 4; i++)
        #pragma unroll
        for (int j = 0; j < 4; j++) {
            float mean = sum[i][j] * 0.2f;
            float var  = fmaxf(sq[i][j] - 5.0f * mean * mean, 0.0f) * 0.25f; // ddof=1
            float r    = mean * expf(-sqrtf(var));
            int q = q0 + ty * 4 + i;
            int p = p0 + tx * 4 + j;
            out[(size_t)q * N_P + p] = r;
        }
}

// ---------------------------------------------------------------------------
extern "C" void kernel_launch(void* const* d_in, const int* in_sizes, int n_in,
                              void* d_out, int out_size)
{
    const float* Q  = (const float*)d_in[0];
    const float* P  = (const float*)d_in[1];
    const float* W1 = (const float*)d_in[2];
    const float* b1 = (const float*)d_in[3];
    const float* W2 = (const float*)d_in[4];
    const float* b2 = (const float*)d_in[5];
    float* out = (float*)d_out;

    dim3 g1(N_Q / GR + N_P / GR, NM, KSPLIT);     // (18, 5, 8) = 720 blocks
    gemm_hqp_kernel<<<g1, 256>>>(Q, P, W1, b1);

    sum_partials_kernel<<<(HQ4 + HP4) / 256, 256>>>();   // 720 blocks

    cudaFuncSetAttribute(final_kernel,
                         cudaFuncAttributeMaxDynamicSharedMemorySize, SMEM_BYTES);
    dim3 g3(N_Q / BQ, N_P / BP);                  // (32, 4) = 128 blocks
    final_kernel<<<g3, 256, SMEM_BYTES>>>(W2, b2, out);
}

// round 6
// speedup vs baseline: 1.9486x; 1.0016x over previous
#include <cuda_runtime.h>
#include <cstdint>

#define N_Q   2048
#define N_P   256
#define EMB   512
#define NM    5
#define HID   64
#define KSPLIT 4
#define GK    (EMB / KSPLIT)     // 128 K per gemm block

// Scratch (allocation-free rule: __device__ globals)
__device__ float g_hq[KSPLIT][NM * N_Q * HID];   // partials, 4 x 2.62 MB
__device__ float g_hp[KSPLIT][NM * N_P * HID];   // partials, 4 x 0.33 MB
__device__ float g_hqs[NM * N_Q * HID];          // summed
__device__ float g_hps[NM * N_P * HID];          // summed

// ---------------------------------------------------------------------------
// Kernel 1: GEMM partials.
// Tile: 128 rows x 64 h, 256 threads, 8x4 outputs/thread, K=128 per block
// staged in two 64-k chunks. grid = (18, 5, 4) = 360 blocks (one wave).
// ---------------------------------------------------------------------------
#define GR  128
#define KC  64    // k-chunk staged at a time

__global__ __launch_bounds__(256) void gemm_hqp_kernel(
    const float* __restrict__ Q, const float* __restrict__ P,
    const float* __restrict__ W1, const float* __restrict__ b1)
{
    __shared__ float As[KC * GR];   // 32 KB
    __shared__ float Ws[KC * HID];  // 16 KB

    const int m  = blockIdx.y;
    const int kh = blockIdx.z;
    const int rt = blockIdx.x;
    const bool is_q = rt < (N_Q / GR);   // 16 q-tiles, 2 p-tiles

    const float* src;
    int row0;
    float* dst;
    if (is_q) {
        src = Q;  row0 = rt * GR;
        dst = &g_hq[kh][(size_t)(m * N_Q + row0) * HID];
    } else {
        src = P;  row0 = (rt - N_Q / GR) * GR;
        dst = &g_hp[kh][(size_t)(m * N_P + row0) * HID];
    }
    const float* Sb = src + (size_t)row0 * EMB + kh * GK;
    const float* Wb = W1 + (size_t)m * HID * (2 * EMB) + (is_q ? 0 : EMB) + kh * GK;

    const int tid = threadIdx.x;
    const int tx  = tid & 15;    // h-group: h = tx*4 .. +3
    const int ty  = tid >> 4;    // row-group: rows ty*8 .. +7

    float acc[8][4] = {};

    for (int kt = 0; kt < GK; kt += KC) {
        if (kt) __syncthreads();
        // --- Stage input tile: 128 rows x 64 k = 2048 float4, 8/thread ---
        #pragma unroll
        for (int it = 0; it < 8; it++) {
            int idx = tid + it * 256;
            int row = idx >> 4;          // 0..127
            int c4  = idx & 15;          // 0..15
            float4 v = *(const float4*)(Sb + (size_t)row * EMB + kt + c4 * 4);
            int col = (row & 3) | ((((row >> 2) ^ (c4 & 7)) & 31) << 2);
            const float* vf = (const float*)&v;
            #pragma unroll
            for (int j = 0; j < 4; j++)
                As[(c4 * 4 + j) * GR + col] = vf[j];
        }
        // --- Stage W tile: 64 h x 64 k = 1024 float4, 4/thread ---
        #pragma unroll
        for (int it = 0; it < 4; it++) {
            int idx = tid + it * 256;
            int h   = idx >> 4;          // 0..63
            int c4  = idx & 15;
            float4 v = *(const float4*)(Wb + (size_t)h * (2 * EMB) + kt + c4 * 4);
            int colh = (h & 3) | ((((h >> 2) ^ (c4 & 7)) & 15) << 2);
            const float* vf = (const float*)&v;
            #pragma unroll
            for (int j = 0; j < 4; j++)
                Ws[(c4 * 4 + j) * HID + colh] = vf[j];
        }
        __syncthreads();

        #pragma unroll 4
        for (int k4 = 0; k4 < 16; k4++) {
            const int s   = k4 & 7;
            const int ca0 = (((ty * 2 + 0) ^ s) & 31) << 2;
            const int ca1 = (((ty * 2 + 1) ^ s) & 31) << 2;
            const int cb  = ((tx ^ s) & 15) << 2;
            #pragma unroll
            for (int j = 0; j < 4; j++) {
                const int k = k4 * 4 + j;
                float4 a0 = *(const float4*)&As[k * GR + ca0];
                float4 a1 = *(const float4*)&As[k * GR + ca1];
                float4 b  = *(const float4*)&Ws[k * HID + cb];
                const float* af0 = (const float*)&a0;
                const float* af1 = (const float*)&a1;
                const float* bf  = (const float*)&b;
                #pragma unroll
                for (int i = 0; i < 4; i++)
                    #pragma unroll
                    for (int c = 0; c < 4; c++) {
                        acc[i][c]     += af0[i] * bf[c];
                        acc[i + 4][c] += af1[i] * bf[c];
                    }
            }
        }
    }

    if (is_q && kh == 0) {
        float4 bv = *(const float4*)(b1 + m * HID + tx * 4);
        #pragma unroll
        for (int i = 0; i < 8; i++) {
            acc[i][0] += bv.x; acc[i][1] += bv.y;
            acc[i][2] += bv.z; acc[i][3] += bv.w;
        }
    }
    #pragma unroll
    for (int i = 0; i < 8; i++)
        *(float4*)(dst + (size_t)(ty * 8 + i) * HID + tx * 4) =
            make_float4(acc[i][0], acc[i][1], acc[i][2], acc[i][3]);
}

// ---------------------------------------------------------------------------
// Kernel 2: sum the 4 K-split partials (L2-resident).
// ---------------------------------------------------------------------------
#define HQ4 (NM * N_Q * HID / 4)   // 163840 float4
#define HP4 (NM * N_P * HID / 4)   // 20480  float4

__global__ __launch_bounds__(256) void sum_partials_kernel()
{
    int i = blockIdx.x * 256 + threadIdx.x;
    if (i < HQ4) {
        float4 a = ((const float4*)g_hq[0])[i];
        #pragma unroll
        for (int s = 1; s < KSPLIT; s++) {
            float4 b = ((const float4*)g_hq[s])[i];
            a.x += b.x; a.y += b.y; a.z += b.z; a.w += b.w;
        }
        ((float4*)g_hqs)[i] = a;
    } else {
        int j = i - HQ4;
        float4 a = ((const float4*)g_hp[0])[j];
        #pragma unroll
        for (int s = 1; s < KSPLIT; s++) {
            float4 b = ((const float4*)g_hp[s])[j];
            a.x += b.x; a.y += b.y; a.z += b.z; a.w += b.w;
        }
        ((float4*)g_hps)[j] = a;
    }
}

// ---------------------------------------------------------------------------
// Kernel 3: fused relu-combine + h-reduction + ensemble stats.
// Tile: 64q x 32p, 256 threads, 4x2 outputs/thread.
// Per-m triple-buffered cp.async staging; packed f32x2 relu-FMA.
// grid = (32, 8) = 256 blocks -> ~2 blocks/SM, 16 warps/SM.
// ---------------------------------------------------------------------------
#define BQ 64
#define BP 32

#define BUF_FLOATS ((BQ + BP) * HID)              // 6144 floats = 24 KB
#define SMEM_FLOATS (3 * BUF_FLOATS + NM * HID + 8)
#define SMEM_BYTES  (SMEM_FLOATS * 4)

// relu(s)*w accumulation, packed 2 x fp32:
//   relu(s) * w == (s + |s|) * (w * 0.5)   (bit-exact)
#define RELU_FMA2(acc, x2, y2, w2)                                    \
    asm("{\n\t"                                                       \
        ".reg .b64 s, a;\n\t"                                         \
        "add.rn.f32x2 s, %1, %2;\n\t"                                 \
        "and.b64 a, s, 0x7FFFFFFF7FFFFFFF;\n\t"                       \
        "add.rn.f32x2 s, s, a;\n\t"                                   \
        "fma.rn.f32x2 %0, s, %3, %0;\n\t"                             \
        "}"                                                           \
        : "+l"(acc) : "l"(x2), "l"(y2), "l"(w2))

__device__ __forceinline__ void cpa16(void* smem_ptr, const void* gptr) {
    uint32_t s = (uint32_t)__cvta_generic_to_shared(smem_ptr);
    asm volatile("cp.async.cg.shared.global [%0], [%1], 16;" :: "r"(s), "l"(gptr));
}

__global__ __launch_bounds__(256) void final_kernel(
    const float* __restrict__ W2, const float* __restrict__ b2,
    float* __restrict__ out)
{
    extern __shared__ float smem_f[];
    float* s_w2 = smem_f + 3 * BUF_FLOATS;
    float* s_b2 = s_w2 + NM * HID;

    const int tid = threadIdx.x;
    const int q0  = blockIdx.x * BQ;
    const int p0  = blockIdx.y * BP;
    const int tyq = tid >> 4;   // 0..15 -> q rows tyq*4 .. +3
    const int txp = tid & 15;   // 0..15 -> p rows txp*2, txp*2+1

    for (int i = tid; i < NM * HID; i += 256) s_w2[i] = 0.5f * W2[i];
    if (tid < NM) s_b2[tid] = b2[tid];

    // stage one model's tiles: x: 64x16 f4 = 1024, y: 32x16 f4 = 512 -> 6/thread
    auto stage = [&](int m, int b) {
        float* base = smem_f + b * BUF_FLOATS;
        #pragma unroll
        for (int k = 0; k < 6; k++) {
            int idx = tid + k * 256;
            const float* g;
            float* s;
            if (idx < 1024) {
                int row = idx >> 4;
                int c4  = idx & 15;
                int sc  = ((c4 ^ (row >> 2)) & 15) * 4;
                g = g_hqs + ((size_t)(m * N_Q + q0 + row)) * HID + c4 * 4;
                s = base + row * HID + sc;
            } else {
                int t   = idx - 1024;
                int row = t >> 4;          // 0..31
                int c4  = t & 15;
                int sc  = ((c4 ^ (row >> 2)) & 15) * 4;
                g = g_hps + ((size_t)(m * N_P + p0 + row)) * HID + c4 * 4;
                s = base + (BQ + row) * HID + sc;
            }
            cpa16(s, g);
        }
        asm volatile("cp.async.commit_group;");
    };

    stage(0, 0);
    stage(1, 1);

    float sum[4][2] = {};
    float sq [4][2] = {};

    for (int m = 0; m < NM; m++) {
        if (m + 2 < NM) {
            stage(m + 2, (m + 2) % 3);
            asm volatile("cp.async.wait_group 2;");
        } else if (m + 1 < NM) {
            asm volatile("cp.async.wait_group 1;");
        } else {
            asm volatile("cp.async.wait_group 0;");
        }
        __syncthreads();

        const float* bx   = smem_f + (m % 3) * BUF_FLOATS;
        const float* xrow = bx + (tyq * 4) * HID;
        const float* yrow = bx + (BQ + txp * 2) * HID;
        const float* wrow = s_w2 + m * HID;

        unsigned long long acc[4][2] = {};

        #pragma unroll 4
        for (int c4 = 0; c4 < 16; c4++) {
            int cx = ((c4 ^ tyq) & 15) * 4;
            int cy = ((c4 ^ (txp >> 1)) & 15) * 4;
            ulonglong2 X[4], Y[2];
            #pragma unroll
            for (int i = 0; i < 4; i++)
                X[i] = *(const ulonglong2*)(xrow + i * HID + cx);
            #pragma unroll
            for (int j = 0; j < 2; j++)
                Y[j] = *(const ulonglong2*)(yrow + j * HID + cy);
            ulonglong2 Wv = *(const ulonglong2*)(wrow + c4 * 4);

            #pragma unroll
            for (int i = 0; i < 4; i++)
                #pragma unroll
                for (int j = 0; j < 2; j++) {
                    RELU_FMA2(acc[i][j], X[i].x, Y[j].x, Wv.x);
                    RELU_FMA2(acc[i][j], X[i].y, Y[j].y, Wv.y);
                }
        }

        float bb = s_b2[m];
        #pragma unroll
        for (int i = 0; i < 4; i++)
            #pragma unroll
            for (int j = 0; j < 2; j++) {
                unsigned long long a = acc[i][j];
                float lo = __uint_as_float((unsigned)(a & 0xFFFFFFFFull));
                float hi = __uint_as_float((unsigned)(a >> 32));
                float o  = lo + hi + bb;
                sum[i][j] += o;
                sq [i][j] += o * o;
            }

        __syncthreads();   // buf m%3 free for stage(m+3) next iter
    }

    #pragma unroll
    for (int i = 0; i < 4; i++)
        #pragma unroll
        for (int j = 0; j < 2; j++) {
            float mean = sum[i][j] * 0.2f;
            float var  = fmaxf(sq[i][j] - 5.0f * mean * mean, 0.0f) * 0.25f; // ddof=1
            float r    = mean * expf(-sqrtf(var));
            int q = q0 + tyq * 4 + i;
            int p = p0 + txp * 2 + j;
            out[(size_t)q * N_P + p] = r;
        }
}

// ---------------------------------------------------------------------------
extern "C" void kernel_launch(void* const* d_in, const int* in_sizes, int n_in,
                              void* d_out, int out_size)
{
    const float* Q  = (const float*)d_in[0];
    const float* P  = (const float*)d_in[1];
    const float* W1 = (const float*)d_in[2];
    const float* b1 = (const float*)d_in[3];
    const float* W2 = (const float*)d_in[4];
    const float* b2 = (const float*)d_in[5];
    float* out = (float*)d_out;

    dim3 g1(N_Q / GR + N_P / GR, NM, KSPLIT);     // (18, 5, 4) = 360 blocks
    gemm_hqp_kernel<<<g1, 256>>>(Q, P, W1, b1);

    sum_partials_kernel<<<(HQ4 + HP4) / 256, 256>>>();   // 720 blocks

    cudaFuncSetAttribute(final_kernel,
                         cudaFuncAttributeMaxDynamicSharedMemorySize, SMEM_BYTES);
    dim3 g3(N_Q / BQ, N_P / BP);                  // (32, 8) = 256 blocks
    final_kernel<<<g3, 256, SMEM_BYTES>>>(W2, b2, out);
}

// round 7
// speedup vs baseline: 2.3185x; 1.1898x over previous
#include <cuda_runtime.h>
#include <cstdint>

#define N_Q   2048
#define N_P   256
#define EMB   512
#define NM    5
#define HID   64
#define KSPLIT 8
#define GK    (EMB / KSPLIT)     // 64 K per gemm block

// Scratch (allocation-free rule: __device__ globals)
__device__ float g_hq[KSPLIT][NM * N_Q * HID];   // partials, 8 x 2.62 MB
__device__ float g_hp[KSPLIT][NM * N_P * HID];   // partials, 8 x 0.33 MB
__device__ float g_hqs[NM * N_Q * HID];          // summed
__device__ float g_hps[NM * N_P * HID];          // summed

// ---------------------------------------------------------------------------
// Kernel 1: GEMM partials (R5 config — measured 23.6us).
// Tile: 128 rows x 64 h, 256 threads, 8x4 outputs/thread, K=64 per block.
// Whole-K staged once (no mid-loop syncs). grid = (18, 5, 8) = 720 blocks.
// ---------------------------------------------------------------------------
#define GR 128

__global__ __launch_bounds__(256) void gemm_hqp_kernel(
    const float* __restrict__ Q, const float* __restrict__ P,
    const float* __restrict__ W1, const float* __restrict__ b1)
{
    __shared__ float As[GK * GR];   // 32 KB
    __shared__ float Ws[GK * HID];  // 16 KB

    const int m  = blockIdx.y;
    const int kh = blockIdx.z;
    const int rt = blockIdx.x;
    const bool is_q = rt < (N_Q / GR);   // 16 q-tiles, 2 p-tiles

    const float* src;
    int row0;
    float* dst;
    if (is_q) {
        src = Q;  row0 = rt * GR;
        dst = &g_hq[kh][(size_t)(m * N_Q + row0) * HID];
    } else {
        src = P;  row0 = (rt - N_Q / GR) * GR;
        dst = &g_hp[kh][(size_t)(m * N_P + row0) * HID];
    }
    const float* Sb = src + (size_t)row0 * EMB + kh * GK;
    const float* Wb = W1 + (size_t)m * HID * (2 * EMB) + (is_q ? 0 : EMB) + kh * GK;

    const int tid = threadIdx.x;
    const int tx  = tid & 15;    // h-group: h = tx*4 .. +3
    const int ty  = tid >> 4;    // row-group: rows ty*8 .. +7

    // --- Stage input tile: 128 rows x 64 k = 2048 float4, 8/thread ---
    #pragma unroll
    for (int it = 0; it < 8; it++) {
        int idx = tid + it * 256;
        int row = idx >> 4;          // 0..127
        int c4  = idx & 15;          // 0..15
        float4 v = *(const float4*)(Sb + (size_t)row * EMB + c4 * 4);
        int col = (row & 3) | ((((row >> 2) ^ (c4 & 7)) & 31) << 2);
        const float* vf = (const float*)&v;
        #pragma unroll
        for (int j = 0; j < 4; j++)
            As[(c4 * 4 + j) * GR + col] = vf[j];
    }
    // --- Stage W tile: 64 h x 64 k = 1024 float4, 4/thread ---
    #pragma unroll
    for (int it = 0; it < 4; it++) {
        int idx = tid + it * 256;
        int h   = idx >> 4;          // 0..63
        int c4  = idx & 15;
        float4 v = *(const float4*)(Wb + (size_t)h * (2 * EMB) + c4 * 4);
        int colh = (h & 3) | ((((h >> 2) ^ (c4 & 7)) & 15) << 2);
        const float* vf = (const float*)&v;
        #pragma unroll
        for (int j = 0; j < 4; j++)
            Ws[(c4 * 4 + j) * HID + colh] = vf[j];
    }
    __syncthreads();

    float acc[8][4] = {};

    #pragma unroll 4
    for (int k4 = 0; k4 < 16; k4++) {
        const int s   = k4 & 7;
        const int ca0 = (((ty * 2 + 0) ^ s) & 31) << 2;
        const int ca1 = (((ty * 2 + 1) ^ s) & 31) << 2;
        const int cb  = ((tx ^ s) & 15) << 2;
        #pragma unroll
        for (int j = 0; j < 4; j++) {
            const int k = k4 * 4 + j;
            float4 a0 = *(const float4*)&As[k * GR + ca0];
            float4 a1 = *(const float4*)&As[k * GR + ca1];
            float4 b  = *(const float4*)&Ws[k * HID + cb];
            const float* af0 = (const float*)&a0;
            const float* af1 = (const float*)&a1;
            const float* bf  = (const float*)&b;
            #pragma unroll
            for (int i = 0; i < 4; i++)
                #pragma unroll
                for (int c = 0; c < 4; c++) {
                    acc[i][c]     += af0[i] * bf[c];
                    acc[i + 4][c] += af1[i] * bf[c];
                }
        }
    }

    if (is_q && kh == 0) {
        float4 bv = *(const float4*)(b1 + m * HID + tx * 4);
        #pragma unroll
        for (int i = 0; i < 8; i++) {
            acc[i][0] += bv.x; acc[i][1] += bv.y;
            acc[i][2] += bv.z; acc[i][3] += bv.w;
        }
    }
    #pragma unroll
    for (int i = 0; i < 8; i++)
        *(float4*)(dst + (size_t)(ty * 8 + i) * HID + tx * 4) =
            make_float4(acc[i][0], acc[i][1], acc[i][2], acc[i][3]);
}

// ---------------------------------------------------------------------------
// Kernel 2: sum the 8 K-split partials (L2-resident).
// ---------------------------------------------------------------------------
#define HQ4 (NM * N_Q * HID / 4)   // 163840 float4
#define HP4 (NM * N_P * HID / 4)   // 20480  float4

__global__ __launch_bounds__(256) void sum_partials_kernel()
{
    int i = blockIdx.x * 256 + threadIdx.x;
    if (i < HQ4) {
        float4 a = ((const float4*)g_hq[0])[i];
        #pragma unroll
        for (int s = 1; s < KSPLIT; s++) {
            float4 b = ((const float4*)g_hq[s])[i];
            a.x += b.x; a.y += b.y; a.z += b.z; a.w += b.w;
        }
        ((float4*)g_hqs)[i] = a;
    } else {
        int j = i - HQ4;
        float4 a = ((const float4*)g_hp[0])[j];
        #pragma unroll
        for (int s = 1; s < KSPLIT; s++) {
            float4 b = ((const float4*)g_hp[s])[j];
            a.x += b.x; a.y += b.y; a.z += b.z; a.w += b.w;
        }
        ((float4*)g_hps)[j] = a;
    }
}

// ---------------------------------------------------------------------------
// Kernel 3: fused relu-combine + h-reduction + ensemble stats.
// Tile: 64q x 32p, 256 threads, 4x2 outputs/thread.
// Per-m triple-buffered cp.async staging; pipe-balanced relu-FMA:
//   add.rn.f32x2 (fma pipe) + 2x scalar max (alu pipe) + fma.rn.f32x2 (fma)
// grid = (32, 8) = 256 blocks.
// ---------------------------------------------------------------------------
#define BQ 64
#define BP 32

#define BUF_FLOATS ((BQ + BP) * HID)              // 6144 floats = 24 KB
#define SMEM_FLOATS (3 * BUF_FLOATS + NM * HID + 8)
#define SMEM_BYTES  (SMEM_FLOATS * 4)

// acc2 += relu(x2 + y2) * w2, packed; relu via scalar FMNMX on the halves
// (alu pipe) to keep the fma pipe at 2 ops per group.
#define RELU_FMA2(acc, x2, y2, w2)                                    \
    asm("{\n\t"                                                       \
        ".reg .b64 s;\n\t"                                            \
        ".reg .f32 lo, hi;\n\t"                                       \
        "add.rn.f32x2 s, %1, %2;\n\t"                                 \
        "mov.b64 {lo, hi}, s;\n\t"                                    \
        "max.f32 lo, lo, 0f00000000;\n\t"                             \
        "max.f32 hi, hi, 0f00000000;\n\t"                             \
        "mov.b64 s, {lo, hi};\n\t"                                    \
        "fma.rn.f32x2 %0, s, %3, %0;\n\t"                             \
        "}"                                                           \
        : "+l"(acc) : "l"(x2), "l"(y2), "l"(w2))

__device__ __forceinline__ void cpa16(void* smem_ptr, const void* gptr) {
    uint32_t s = (uint32_t)__cvta_generic_to_shared(smem_ptr);
    asm volatile("cp.async.cg.shared.global [%0], [%1], 16;" :: "r"(s), "l"(gptr));
}

__global__ __launch_bounds__(256) void final_kernel(
    const float* __restrict__ W2, const float* __restrict__ b2,
    float* __restrict__ out)
{
    extern __shared__ float smem_f[];
    float* s_w2 = smem_f + 3 * BUF_FLOATS;
    float* s_b2 = s_w2 + NM * HID;

    const int tid = threadIdx.x;
    const int q0  = blockIdx.x * BQ;
    const int p0  = blockIdx.y * BP;
    const int tyq = tid >> 4;   // 0..15 -> q rows tyq*4 .. +3
    const int txp = tid & 15;   // 0..15 -> p rows txp*2, txp*2+1

    for (int i = tid; i < NM * HID; i += 256) s_w2[i] = W2[i];
    if (tid < NM) s_b2[tid] = b2[tid];

    // stage one model's tiles: x: 64x16 f4 = 1024, y: 32x16 f4 = 512 -> 6/thread
    auto stage = [&](int m, int b) {
        float* base = smem_f + b * BUF_FLOATS;
        #pragma unroll
        for (int k = 0; k < 6; k++) {
            int idx = tid + k * 256;
            const float* g;
            float* s;
            if (idx < 1024) {
                int row = idx >> 4;
                int c4  = idx & 15;
                int sc  = ((c4 ^ (row >> 2)) & 15) * 4;
                g = g_hqs + ((size_t)(m * N_Q + q0 + row)) * HID + c4 * 4;
                s = base + row * HID + sc;
            } else {
                int t   = idx - 1024;
                int row = t >> 4;          // 0..31
                int c4  = t & 15;
                int sc  = ((c4 ^ (row >> 2)) & 15) * 4;
                g = g_hps + ((size_t)(m * N_P + p0 + row)) * HID + c4 * 4;
                s = base + (BQ + row) * HID + sc;
            }
            cpa16(s, g);
        }
        asm volatile("cp.async.commit_group;");
    };

    stage(0, 0);
    stage(1, 1);

    float sum[4][2] = {};
    float sq [4][2] = {};

    for (int m = 0; m < NM; m++) {
        if (m + 2 < NM) {
            stage(m + 2, (m + 2) % 3);
            asm volatile("cp.async.wait_group 2;");
        } else if (m + 1 < NM) {
            asm volatile("cp.async.wait_group 1;");
        } else {
            asm volatile("cp.async.wait_group 0;");
        }
        __syncthreads();

        const float* bx   = smem_f + (m % 3) * BUF_FLOATS;
        const float* xrow = bx + (tyq * 4) * HID;
        const float* yrow = bx + (BQ + txp * 2) * HID;
        const float* wrow = s_w2 + m * HID;

        unsigned long long acc[4][2] = {};

        #pragma unroll 4
        for (int c4 = 0; c4 < 16; c4++) {
            int cx = ((c4 ^ tyq) & 15) * 4;
            int cy = ((c4 ^ (txp >> 1)) & 15) * 4;
            ulonglong2 X[4], Y[2];
            #pragma unroll
            for (int i = 0; i < 4; i++)
                X[i] = *(const ulonglong2*)(xrow + i * HID + cx);
            #pragma unroll
            for (int j = 0; j < 2; j++)
                Y[j] = *(const ulonglong2*)(yrow + j * HID + cy);
            ulonglong2 Wv = *(const ulonglong2*)(wrow + c4 * 4);

            #pragma unroll
            for (int i = 0; i < 4; i++)
                #pragma unroll
                for (int j = 0; j < 2; j++) {
                    RELU_FMA2(acc[i][j], X[i].x, Y[j].x, Wv.x);
                    RELU_FMA2(acc[i][j], X[i].y, Y[j].y, Wv.y);
                }
        }

        float bb = s_b2[m];
        #pragma unroll
        for (int i = 0; i < 4; i++)
            #pragma unroll
            for (int j = 0; j < 2; j++) {
                unsigned long long a = acc[i][j];
                float lo = __uint_as_float((unsigned)(a & 0xFFFFFFFFull));
                float hi = __uint_as_float((unsigned)(a >> 32));
                float o  = lo + hi + bb;
                sum[i][j] += o;
                sq [i][j] += o * o;
            }

        __syncthreads();   // buf m%3 free for stage(m+3) next iter
    }

    #pragma unroll
    for (int i = 0; i < 4; i++)
        #pragma unroll
        for (int j = 0; j < 2; j++) {
            float mean = sum[i][j] * 0.2f;
            float var  = fmaxf(sq[i][j] - 5.0f * mean * mean, 0.0f) * 0.25f; // ddof=1
            float r    = mean * expf(-sqrtf(var));
            int q = q0 + tyq * 4 + i;
            int p = p0 + txp * 2 + j;
            out[(size_t)q * N_P + p] = r;
        }
}

// ---------------------------------------------------------------------------
extern "C" void kernel_launch(void* const* d_in, const int* in_sizes, int n_in,
                              void* d_out, int out_size)
{
    const float* Q  = (const float*)d_in[0];
    const float* P  = (const float*)d_in[1];
    const float* W1 = (const float*)d_in[2];
    const float* b1 = (const float*)d_in[3];
    const float* W2 = (const float*)d_in[4];
    const float* b2 = (const float*)d_in[5];
    float* out = (float*)d_out;

    dim3 g1(N_Q / GR + N_P / GR, NM, KSPLIT);     // (18, 5, 8) = 720 blocks
    gemm_hqp_kernel<<<g1, 256>>>(Q, P, W1, b1);

    sum_partials_kernel<<<(HQ4 + HP4) / 256, 256>>>();   // 720 blocks

    cudaFuncSetAttribute(final_kernel,
                         cudaFuncAttributeMaxDynamicSharedMemorySize, SMEM_BYTES);
    dim3 g3(N_Q / BQ, N_P / BP);                  // (32, 8) = 256 blocks
    final_kernel<<<g3, 256, SMEM_BYTES>>>(W2, b2, out);
}

// round 9
// speedup vs baseline: 2.6628x; 1.1485x over previous
#include <cuda_runtime.h>
#include <cstdint>

#define N_Q   2048
#define N_P   256
#define EMB   512
#define NM    5
#define HID   64

// Scratch (allocation-free rule: __device__ globals)
__device__ float g_hqs[NM * N_Q * HID];          // hq + b1
__device__ float g_hps[NM * N_P * HID];          // hp

// ===========================================================================
// Kernel 1: bf16 HMMA GEMM with 3-term hi/lo split.
//   out = Ahi*Whi + Ahi*Wlo + Alo*Whi   (fp32 accum, err ~2^-18 rel)
// Block: 64 rows x 64 h, 128 threads (4 warps x 16 rows), one m.
// K = 512 in 8 chunks of 64; smem bf16 tiles, swizzle kg ^= row&7.
// grid = (36, 5) = 180 blocks.
// ===========================================================================
#define SM_AHI 0
#define SM_ALO 16384
#define SM_WHI 32768
#define SM_WLO 40960

__device__ __forceinline__ uint32_t smem_u32(const void* p) {
    uint32_t a;
    asm("{ .reg .u64 t; cvta.to.shared.u64 t, %1; cvt.u32.u64 %0, t; }"
        : "=r"(a) : "l"(p));
    return a;
}

#define LDSM4(r, addr)                                                       \
    asm volatile("ldmatrix.sync.aligned.m8n8.x4.shared.b16 "                 \
                 "{%0,%1,%2,%3}, [%4];"                                      \
                 : "=r"((r)[0]), "=r"((r)[1]), "=r"((r)[2]), "=r"((r)[3])    \
                 : "r"(addr))

#define MMA16816(d, a, b0v, b1v)                                             \
    asm volatile("mma.sync.aligned.m16n8k16.row.col.f32.bf16.bf16.f32 "      \
                 "{%0,%1,%2,%3}, {%4,%5,%6,%7}, {%8,%9}, {%0,%1,%2,%3};"     \
                 : "+f"((d)[0]), "+f"((d)[1]), "+f"((d)[2]), "+f"((d)[3])    \
                 : "r"((a)[0]), "r"((a)[1]), "r"((a)[2]), "r"((a)[3]),       \
                   "r"(b0v), "r"(b1v))

// 8 fp32 -> 8 bf16 hi (16B) + 8 bf16 lo (16B)
__device__ __forceinline__ void split8(float4 a, float4 b, uint4& hi, uint4& lo) {
    asm("cvt.rn.bf16x2.f32 %0, %1, %2;" : "=r"(hi.x) : "f"(a.y), "f"(a.x));
    asm("cvt.rn.bf16x2.f32 %0, %1, %2;" : "=r"(hi.y) : "f"(a.w), "f"(a.z));
    asm("cvt.rn.bf16x2.f32 %0, %1, %2;" : "=r"(hi.z) : "f"(b.y), "f"(b.x));
    asm("cvt.rn.bf16x2.f32 %0, %1, %2;" : "=r"(hi.w) : "f"(b.w), "f"(b.z));
    float h0 = __uint_as_float(hi.x << 16), h1 = __uint_as_float(hi.x & 0xFFFF0000u);
    float h2 = __uint_as_float(hi.y << 16), h3 = __uint_as_float(hi.y & 0xFFFF0000u);
    float h4 = __uint_as_float(hi.z << 16), h5 = __uint_as_float(hi.z & 0xFFFF0000u);
    float h6 = __uint_as_float(hi.w << 16), h7 = __uint_as_float(hi.w & 0xFFFF0000u);
    asm("cvt.rn.bf16x2.f32 %0, %1, %2;" : "=r"(lo.x) : "f"(a.y - h1), "f"(a.x - h0));
    asm("cvt.rn.bf16x2.f32 %0, %1, %2;" : "=r"(lo.y) : "f"(a.w - h3), "f"(a.z - h2));
    asm("cvt.rn.bf16x2.f32 %0, %1, %2;" : "=r"(lo.z) : "f"(b.y - h5), "f"(b.x - h4));
    asm("cvt.rn.bf16x2.f32 %0, %1, %2;" : "=r"(lo.w) : "f"(b.w - h7), "f"(b.z - h6));
}

__global__ __launch_bounds__(128) void gemm_mma_kernel(
    const float* __restrict__ Q, const float* __restrict__ P,
    const float* __restrict__ W1, const float* __restrict__ b1)
{
    __shared__ __align__(128) char smem[49152];
    const uint32_t sb = smem_u32(smem);

    const int tid  = threadIdx.x;
    const int wid  = tid >> 5;
    const int lane = tid & 31;

    const int m  = blockIdx.y;
    const int rt = blockIdx.x;
    const bool is_q = rt < (N_Q / 64);   // 32 q-tiles, 4 p-tiles

    const float* src;
    int row0;
    float* dst;
    if (is_q) {
        src = Q;  row0 = rt * 64;
        dst = g_hqs + (size_t)(m * N_Q + row0) * HID;
    } else {
        src = P;  row0 = (rt - N_Q / 64) * 64;
        dst = g_hps + (size_t)(m * N_P + row0) * HID;
    }
    const float* Sb = src + (size_t)row0 * EMB;
    const float* Wb = W1 + (size_t)m * HID * (2 * EMB) + (is_q ? 0 : EMB);

    // Staging slots: idx = tid + i*128 over 512 groups; row = idx>>3, kg = idx&7
    const int st_row = tid >> 3;          // base row for i=0 (rows 0..15)
    const int st_kg  = tid & 7;

    float4 pa[8], pw[8];
    auto ldg_chunk = [&](int c) {
        const int kt = c * 64;
        #pragma unroll
        for (int i = 0; i < 4; i++) {
            int row = st_row + i * 16;
            const float* g  = Sb + (size_t)row * EMB + kt + st_kg * 8;
            const float* gw = Wb + (size_t)row * (2 * EMB) + kt + st_kg * 8;
            pa[2 * i]     = *(const float4*)g;
            pa[2 * i + 1] = *(const float4*)(g + 4);
            pw[2 * i]     = *(const float4*)gw;
            pw[2 * i + 1] = *(const float4*)(gw + 4);
        }
    };
    auto sts_chunk = [&]() {
        #pragma unroll
        for (int i = 0; i < 4; i++) {
            int row = st_row + i * 16;
            uint32_t off = (uint32_t)(row * 128 + ((st_kg ^ (row & 7)) << 4));
            uint4 hi, lo;
            split8(pa[2 * i], pa[2 * i + 1], hi, lo);
            *(uint4*)(smem + SM_AHI + off) = hi;
            *(uint4*)(smem + SM_ALO + off) = lo;
            split8(pw[2 * i], pw[2 * i + 1], hi, lo);
            *(uint4*)(smem + SM_WHI + off) = hi;
            *(uint4*)(smem + SM_WLO + off) = lo;
        }
    };

    // ldmatrix lane address components
    const int rA   = wid * 16 + (lane & 15);      // A row this lane addresses
    const int rx7A = rA & 7;
    const int kselA = lane >> 4;                  // +1 kg for matrices 2,3
    const int rB_loc  = ((lane >> 4) & 1) * 8 + (lane & 7);
    const int kgB_add = (lane >> 3) & 1;

    float acc[8][4] = {};

    ldg_chunk(0);

    for (int c = 0; c < 8; c++) {
        sts_chunk();
        __syncthreads();
        if (c < 7) ldg_chunk(c + 1);   // prefetch next chunk during MMA

        #pragma unroll
        for (int ks = 0; ks < 4; ks++) {
            const int kgA = ks * 2 + kselA;
            const uint32_t aoff = (uint32_t)(rA * 128 + ((kgA ^ rx7A) << 4));
            uint32_t ahi[4], alo[4];
            LDSM4(ahi, sb + SM_AHI + aoff);
            LDSM4(alo, sb + SM_ALO + aoff);

            #pragma unroll
            for (int j = 0; j < 4; j++) {
                const int rB  = j * 16 + rB_loc;
                const int kgB = ks * 2 + kgB_add;
                const uint32_t boff = (uint32_t)(rB * 128 + ((kgB ^ (rB & 7)) << 4));
                uint32_t bhi[4], blo[4];
                LDSM4(bhi, sb + SM_WHI + boff);
                LDSM4(blo, sb + SM_WLO + boff);

                MMA16816(acc[2 * j],     ahi, bhi[0], bhi[1]);
                MMA16816(acc[2 * j],     ahi, blo[0], blo[1]);
                MMA16816(acc[2 * j],     alo, bhi[0], bhi[1]);
                MMA16816(acc[2 * j + 1], ahi, bhi[2], bhi[3]);
                MMA16816(acc[2 * j + 1], ahi, blo[2], blo[3]);
                MMA16816(acc[2 * j + 1], alo, bhi[2], bhi[3]);
            }
        }
        __syncthreads();
    }

    // Epilogue: d frag: (d0,d1)=(row L/4, col (L%4)*2,+1), (d2,d3)=row+8
    const int er = lane >> 2;
    const int ec = (lane & 3) * 2;
    float* d0 = dst + (size_t)(wid * 16 + er) * HID;
    float* d1 = dst + (size_t)(wid * 16 + er + 8) * HID;
    #pragma unroll
    for (int nf = 0; nf < 8; nf++) {
        float bx = 0.f, by = 0.f;
        if (is_q) {
            float2 bv = *(const float2*)(b1 + m * HID + nf * 8 + ec);
            bx = bv.x; by = bv.y;
        }
        *(float2*)(d0 + nf * 8 + ec) = make_float2(acc[nf][0] + bx, acc[nf][1] + by);
        *(float2*)(d1 + nf * 8 + ec) = make_float2(acc[nf][2] + bx, acc[nf][3] + by);
    }
}

// ===========================================================================
// Kernel 2: fused relu-combine + h-reduction + ensemble stats (R7, measured).
// Tile: 64q x 32p, 256 threads, 4x2/thread; triple-buffer cp.async;
// pipe-balanced relu-FMA. grid = (32, 8) = 256 blocks.
// ===========================================================================
#define BQ 64
#define BP 32
#define BUF_FLOATS ((BQ + BP) * HID)
#define SMEM_FLOATS (3 * BUF_FLOATS + NM * HID + 8)
#define SMEM_BYTES  (SMEM_FLOATS * 4)

#define RELU_FMA2(acc, x2, y2, w2)                                    \
    asm("{\n\t"                                                       \
        ".reg .b64 s;\n\t"                                            \
        ".reg .f32 lo, hi;\n\t"                                       \
        "add.rn.f32x2 s, %1, %2;\n\t"                                 \
        "mov.b64 {lo, hi}, s;\n\t"                                    \
        "max.f32 lo, lo, 0f00000000;\n\t"                             \
        "max.f32 hi, hi, 0f00000000;\n\t"                             \
        "mov.b64 s, {lo, hi};\n\t"                                    \
        "fma.rn.f32x2 %0, s, %3, %0;\n\t"                             \
        "}"                                                           \
        : "+l"(acc) : "l"(x2), "l"(y2), "l"(w2))

__device__ __forceinline__ void cpa16(void* smem_ptr, const void* gptr) {
    uint32_t s = (uint32_t)__cvta_generic_to_shared(smem_ptr);
    asm volatile("cp.async.cg.shared.global [%0], [%1], 16;" :: "r"(s), "l"(gptr));
}

__global__ __launch_bounds__(256) void final_kernel(
    const float* __restrict__ W2, const float* __restrict__ b2,
    float* __restrict__ out)
{
    extern __shared__ float smem_f[];
    float* s_w2 = smem_f + 3 * BUF_FLOATS;
    float* s_b2 = s_w2 + NM * HID;

    const int tid = threadIdx.x;
    const int q0  = blockIdx.x * BQ;
    const int p0  = blockIdx.y * BP;
    const int tyq = tid >> 4;
    const int txp = tid & 15;

    for (int i = tid; i < NM * HID; i += 256) s_w2[i] = W2[i];
    if (tid < NM) s_b2[tid] = b2[tid];

    auto stage = [&](int m, int b) {
        float* base = smem_f + b * BUF_FLOATS;
        #pragma unroll
        for (int k = 0; k < 6; k++) {
            int idx = tid + k * 256;
            const float* g;
            float* s;
            if (idx < 1024) {
                int row = idx >> 4;
                int c4  = idx & 15;
                int sc  = ((c4 ^ (row >> 2)) & 15) * 4;
                g = g_hqs + ((size_t)(m * N_Q + q0 + row)) * HID + c4 * 4;
                s = base + row * HID + sc;
            } else {
                int t   = idx - 1024;
                int row = t >> 4;
                int c4  = t & 15;
                int sc  = ((c4 ^ (row >> 2)) & 15) * 4;
                g = g_hps + ((size_t)(m * N_P + p0 + row)) * HID + c4 * 4;
                s = base + (BQ + row) * HID + sc;
            }
            cpa16(s, g);
        }
        asm volatile("cp.async.commit_group;");
    };

    stage(0, 0);
    stage(1, 1);

    float sum[4][2] = {};
    float sq [4][2] = {};

    for (int m = 0; m < NM; m++) {
        if (m + 2 < NM) {
            stage(m + 2, (m + 2) % 3);
            asm volatile("cp.async.wait_group 2;");
        } else if (m + 1 < NM) {
            asm volatile("cp.async.wait_group 1;");
        } else {
            asm volatile("cp.async.wait_group 0;");
        }
        __syncthreads();

        const float* bx   = smem_f + (m % 3) * BUF_FLOATS;
        const float* xrow = bx + (tyq * 4) * HID;
        const float* yrow = bx + (BQ + txp * 2) * HID;
        const float* wrow = s_w2 + m * HID;

        unsigned long long acc[4][2] = {};

        #pragma unroll 4
        for (int c4 = 0; c4 < 16; c4++) {
            int cx = ((c4 ^ tyq) & 15) * 4;
            int cy = ((c4 ^ (txp >> 1)) & 15) * 4;
            ulonglong2 X[4], Y[2];
            #pragma unroll
            for (int i = 0; i < 4; i++)
                X[i] = *(const ulonglong2*)(xrow + i * HID + cx);
            #pragma unroll
            for (int j = 0; j < 2; j++)
                Y[j] = *(const ulonglong2*)(yrow + j * HID + cy);
            ulonglong2 Wv = *(const ulonglong2*)(wrow + c4 * 4);

            #pragma unroll
            for (int i = 0; i < 4; i++)
                #pragma unroll
                for (int j = 0; j < 2; j++) {
                    RELU_FMA2(acc[i][j], X[i].x, Y[j].x, Wv.x);
                    RELU_FMA2(acc[i][j], X[i].y, Y[j].y, Wv.y);
                }
        }

        float bb = s_b2[m];
        #pragma unroll
        for (int i = 0; i < 4; i++)
            #pragma unroll
            for (int j = 0; j < 2; j++) {
                unsigned long long a = acc[i][j];
                float lo = __uint_as_float((unsigned)(a & 0xFFFFFFFFull));
                float hi = __uint_as_float((unsigned)(a >> 32));
                float o  = lo + hi + bb;
                sum[i][j] += o;
                sq [i][j] += o * o;
            }

        __syncthreads();
    }

    #pragma unroll
    for (int i = 0; i < 4; i++)
        #pragma unroll
        for (int j = 0; j < 2; j++) {
            float mean = sum[i][j] * 0.2f;
            float var  = fmaxf(sq[i][j] - 5.0f * mean * mean, 0.0f) * 0.25f;
            float r    = mean * expf(-sqrtf(var));
            int q = q0 + tyq * 4 + i;
            int p = p0 + txp * 2 + j;
            out[(size_t)q * N_P + p] = r;
        }
}

// ---------------------------------------------------------------------------
extern "C" void kernel_launch(void* const* d_in, const int* in_sizes, int n_in,
                              void* d_out, int out_size)
{
    const float* Q  = (const float*)d_in[0];
    const float* P  = (const float*)d_in[1];
    const float* W1 = (const float*)d_in[2];
    const float* b1 = (const float*)d_in[3];
    const float* W2 = (const float*)d_in[4];
    const float* b2 = (const float*)d_in[5];
    float* out = (float*)d_out;

    dim3 g1(N_Q / 64 + N_P / 64, NM);             // (36, 5) = 180 blocks
    gemm_mma_kernel<<<g1, 128>>>(Q, P, W1, b1);

    cudaFuncSetAttribute(final_kernel,
                         cudaFuncAttributeMaxDynamicSharedMemorySize, SMEM_BYTES);
    dim3 g3(N_Q / BQ, N_P / BP);                  // (32, 8) = 256 blocks
    final_kernel<<<g3, 256, SMEM_BYTES>>>(W2, b2, out);
}